// round 14
// baseline (speedup 1.0000x reference)
#include <cuda_runtime.h>
#include <cuda_bf16.h>
#include <cstdint>
#include <math.h>

#define Bb 4
#define Nn 8192
#define Cc 512
#define Hh 8
#define Dd 64
#define SPL 4
#define OUT_ELEMS (Bb*Nn*Cc)
#define ATT_ELEMS (Bb*Hh*Dd*Dd)

// ---------------------------------------------------------------------------
// Static scratch
// ---------------------------------------------------------------------------
__device__ float g_Gpart[SPL*Bb*Cc*Cc];     // split-K partials of Gt
__device__ float g_T[Bb*Cc*Cc];
__device__ float g_att[ATT_ELEMS];
__device__ float g_M[Bb*Cc*Cc];             // fused proj*att (fp32)
__device__ float g_b2[Bb*Cc];               // folded bias
__device__ float g_sx[Bb][Cc];
__device__ float g_sc[Bb][Cc];
__device__ float g_cspart[2][8][Bb][Cc];    // colsum split partials (R10 layout)

__device__ __nv_bfloat16 g_ch[Bb*Nn*Cc],  g_cl[Bb*Nn*Cc];    // ctx (K=c major)
__device__ __nv_bfloat16 g_xTh[Bb*Cc*Nn], g_xTl[Bb*Cc*Nn];   // x^T  (K=n major)
__device__ __nv_bfloat16 g_cTh[Bb*Cc*Nn], g_cTl[Bb*Cc*Nn];   // ctx^T
__device__ __nv_bfloat16 g_Gth[Bb*Cc*Cc], g_Gtl[Bb*Cc*Cc];   // Gt h/l
__device__ __nv_bfloat16 g_W2h[Bb*Cc*Cc], g_W2l[Bb*Cc*Cc];   // W2 = M*Wv h/l
__device__ __nv_bfloat16 g_Wqh[Cc*Cc], g_Wql[Cc*Cc];

// ---------------------------------------------------------------------------
// mma.sync m16n8k16 bf16 + ldmatrix (R10-proven)
// ---------------------------------------------------------------------------
__device__ __forceinline__ void mma16816(float* c, const uint32_t* a, const uint32_t* b)
{
    asm volatile(
        "mma.sync.aligned.m16n8k16.row.col.f32.bf16.bf16.f32 "
        "{%0,%1,%2,%3}, {%4,%5,%6,%7}, {%8,%9}, {%0,%1,%2,%3};"
        : "+f"(c[0]), "+f"(c[1]), "+f"(c[2]), "+f"(c[3])
        : "r"(a[0]), "r"(a[1]), "r"(a[2]), "r"(a[3]), "r"(b[0]), "r"(b[1]));
}
__device__ __forceinline__ void ldsm_x4(uint32_t* r, const __nv_bfloat16* p)
{
    uint32_t addr = (uint32_t)__cvta_generic_to_shared(p);
    asm volatile("ldmatrix.sync.aligned.m8n8.x4.shared.b16 {%0,%1,%2,%3}, [%4];"
                 : "=r"(r[0]), "=r"(r[1]), "=r"(r[2]), "=r"(r[3]) : "r"(addr));
}
__device__ __forceinline__ void split_store4(float4 v, __nv_bfloat16* dh,
                                             __nv_bfloat16* dl, size_t i)
{
    float vv[4];
    vv[0] = v.x; vv[1] = v.y; vv[2] = v.z; vv[3] = v.w;
    uint32_t hp[2], lp[2];
    #pragma unroll
    for (int p = 0; p < 2; ++p) {
        __nv_bfloat16 h0 = __float2bfloat16_rn(vv[2*p]);
        __nv_bfloat16 h1 = __float2bfloat16_rn(vv[2*p+1]);
        __nv_bfloat16 l0 = __float2bfloat16_rn(vv[2*p]   - __bfloat162float(h0));
        __nv_bfloat16 l1 = __float2bfloat16_rn(vv[2*p+1] - __bfloat162float(h1));
        hp[p] = (uint32_t)__bfloat16_as_ushort(h0) | ((uint32_t)__bfloat16_as_ushort(h1) << 16);
        lp[p] = (uint32_t)__bfloat16_as_ushort(l0) | ((uint32_t)__bfloat16_as_ushort(l1) << 16);
    }
    *(uint2*)(dh + i) = make_uint2(hp[0], hp[1]);
    *(uint2*)(dl + i) = make_uint2(lp[0], lp[1]);
}

// ---------------------------------------------------------------------------
// GEMM tile (EXACT R10 structure): D[128x128] = sum_k A B^T, split-3 bf16 h/l.
// 256 thr, 8 warps 32x64, Kc=32, 40KB static smem, register prefetch,
// ldmatrix frag loads, fp32 epilogue (+bias).
// ---------------------------------------------------------------------------
#define SK 40
#define TILE_ELEMS (128*SK)

__device__ void tc_gemm_tile(
    const __nv_bfloat16* __restrict__ Ah, const __nv_bfloat16* __restrict__ Al, int lda,
    const __nv_bfloat16* __restrict__ Bh, const __nv_bfloat16* __restrict__ Bl, int ldb,
    int K, int row0, int col0,
    const float* __restrict__ bias,
    float* __restrict__ outF, int ldo)
{
    __shared__ __nv_bfloat16 sm[4*TILE_ELEMS];   // 40960 B static

    const int tid  = threadIdx.x;
    const int lane = tid & 31;
    const int wid  = tid >> 5;
    const int wm   = wid >> 1;
    const int wn   = wid & 1;
    const int gr   = lane >> 2;
    const int kp   = (lane & 3) << 1;
    const int lrow = lane & 15;
    const int lkof = (lane >> 4) * 8;

    const int prow = tid >> 1;
    const int pc0  = (tid & 1) * 16;

    float acc[64];
    #pragma unroll
    for (int i = 0; i < 64; ++i) acc[i] = 0.f;

    uint2 pfa[2][4];
    uint2 pfb[2][4];

    #pragma unroll
    for (int i = 0; i < 4; ++i) {
        pfa[0][i] = *(const uint2*)(Ah + (size_t)(row0+prow)*lda + pc0 + i*4);
        pfa[1][i] = *(const uint2*)(Al + (size_t)(row0+prow)*lda + pc0 + i*4);
        pfb[0][i] = *(const uint2*)(Bh + (size_t)(col0+prow)*ldb + pc0 + i*4);
        pfb[1][i] = *(const uint2*)(Bl + (size_t)(col0+prow)*ldb + pc0 + i*4);
    }

    const int nch = K / 32;
    for (int c = 0; c < nch; ++c) {
        __syncthreads();
        #pragma unroll
        for (int i = 0; i < 4; ++i) {
            *(uint2*)(sm + 0*TILE_ELEMS + prow*SK + pc0 + i*4) = pfa[0][i];
            *(uint2*)(sm + 1*TILE_ELEMS + prow*SK + pc0 + i*4) = pfa[1][i];
            *(uint2*)(sm + 2*TILE_ELEMS + prow*SK + pc0 + i*4) = pfb[0][i];
            *(uint2*)(sm + 3*TILE_ELEMS + prow*SK + pc0 + i*4) = pfb[1][i];
        }
        __syncthreads();

        if (c + 1 < nch) {
            const int k0 = (c + 1) * 32;
            #pragma unroll
            for (int i = 0; i < 4; ++i) {
                pfa[0][i] = *(const uint2*)(Ah + (size_t)(row0+prow)*lda + k0 + pc0 + i*4);
                pfa[1][i] = *(const uint2*)(Al + (size_t)(row0+prow)*lda + k0 + pc0 + i*4);
                pfb[0][i] = *(const uint2*)(Bh + (size_t)(col0+prow)*ldb + k0 + pc0 + i*4);
                pfb[1][i] = *(const uint2*)(Bl + (size_t)(col0+prow)*ldb + k0 + pc0 + i*4);
            }
        }

        const __nv_bfloat16* sAh = sm + 0*TILE_ELEMS;
        const __nv_bfloat16* sAl = sm + 1*TILE_ELEMS;
        const __nv_bfloat16* sBh = sm + 2*TILE_ELEMS;
        const __nv_bfloat16* sBl = sm + 3*TILE_ELEMS;

        #pragma unroll
        for (int k16 = 0; k16 < 32; k16 += 16) {
            uint32_t ah[2][4], al[2][4];
            #pragma unroll
            for (int mt = 0; mt < 2; ++mt) {
                const int m0 = wm*32 + mt*16;
                ldsm_x4(ah[mt], sAh + (m0 + lrow)*SK + k16 + lkof);
                ldsm_x4(al[mt], sAl + (m0 + lrow)*SK + k16 + lkof);
            }
            #pragma unroll
            for (int nt2 = 0; nt2 < 4; ++nt2) {
                const int n0 = wn*64 + nt2*16;
                uint32_t bh4[4], bl4[4];
                ldsm_x4(bh4, sBh + (n0 + lrow)*SK + k16 + lkof);
                ldsm_x4(bl4, sBl + (n0 + lrow)*SK + k16 + lkof);
                uint32_t bhE[2] = {bh4[0], bh4[2]}, bhO[2] = {bh4[1], bh4[3]};
                uint32_t blE[2] = {bl4[0], bl4[2]}, blO[2] = {bl4[1], bl4[3]};
                #pragma unroll
                for (int mt = 0; mt < 2; ++mt) {
                    float* ccE = &acc[(mt*8 + 2*nt2    )*4];
                    float* ccO = &acc[(mt*8 + 2*nt2 + 1)*4];
                    mma16816(ccE, ah[mt], bhE);
                    mma16816(ccE, ah[mt], blE);
                    mma16816(ccE, al[mt], bhE);
                    mma16816(ccO, ah[mt], bhO);
                    mma16816(ccO, ah[mt], blO);
                    mma16816(ccO, al[mt], bhO);
                }
            }
        }
    }

    #pragma unroll
    for (int mt = 0; mt < 2; ++mt) {
        const int r0 = row0 + wm*32 + mt*16 + gr;
        #pragma unroll
        for (int nt = 0; nt < 8; ++nt) {
            const int col = col0 + wn*64 + nt*8 + kp;
            const float* cc = &acc[(mt*8 + nt)*4];
            float b0 = bias ? bias[col]     : 0.f;
            float b1 = bias ? bias[col + 1] : 0.f;
            *(float2*)(outF + (size_t)r0*ldo + col)     = make_float2(cc[0] + b0, cc[1] + b1);
            *(float2*)(outF + (size_t)(r0+8)*ldo + col) = make_float2(cc[2] + b0, cc[3] + b1);
        }
    }
}

// ---------------------------------------------------------------------------
// GEMM wrapper kernels
// ---------------------------------------------------------------------------
__global__ __launch_bounds__(256)
void spart_tc()   // Gt[c2][c1] = sum_n ctx[n,c2] x[n,c1], split-K over n
{
    const int t = blockIdx.x, b = blockIdx.y, s = blockIdx.z;
    const size_t tb = (size_t)b*Cc*Nn + (size_t)s*(Nn/SPL);
    tc_gemm_tile(g_cTh + tb, g_cTl + tb, Nn,
                 g_xTh + tb, g_xTl + tb, Nn,
                 Nn/SPL, (t >> 2)*128, (t & 3)*128,
                 nullptr,
                 g_Gpart + ((size_t)s*Bb + b)*Cc*Cc, Cc);
}

__global__ __launch_bounds__(256)
void T_tc()   // T[b] = Wq @ Gt[b]^T
{
    const int b = blockIdx.z;
    tc_gemm_tile(g_Wqh, g_Wql, Cc,
                 g_Gth + (size_t)b*Cc*Cc, g_Gtl + (size_t)b*Cc*Cc, Cc,
                 Cc, blockIdx.x*128, blockIdx.y*128,
                 nullptr, g_T + (size_t)b*Cc*Cc, Cc);
}

__global__ __launch_bounds__(256)
void out_tc(float* __restrict__ out)   // out[b] = ctx[b] @ W2[b]^T + b2[b]
{
    const int row0 = blockIdx.x*128;
    const int b = row0 >> 13;
    tc_gemm_tile(g_ch, g_cl, Cc,
                 g_W2h + (size_t)b*Cc*Cc, g_W2l + (size_t)b*Cc*Cc, Cc,
                 Cc, row0, blockIdx.y*128,
                 g_b2 + (size_t)b*Cc, out, Cc);
}

// ---------------------------------------------------------------------------
// Conversion kernels (R10-proven)
// ---------------------------------------------------------------------------
__global__ void conv_ctx_kernel(const float* __restrict__ ctx)
{
    const size_t i = ((size_t)blockIdx.x*256 + threadIdx.x)*4;
    split_store4(*(const float4*)(ctx + i), g_ch, g_cl, i);
}

__global__ void conv_wq_kernel(const float* __restrict__ Wq)
{
    const size_t i = ((size_t)blockIdx.x*256 + threadIdx.x)*4;   // 256 blocks: exact
    split_store4(*(const float4*)(Wq + i), g_Wqh, g_Wql, i);
}

__global__ void convT_kernel(const float* __restrict__ x, const float* __restrict__ ctx)
{
    const int z = blockIdx.z;
    const int b = z & 3;
    const float* src = (z < 4) ? x : ctx;
    __nv_bfloat16* dh = (z < 4) ? g_xTh : g_cTh;
    __nv_bfloat16* dl = (z < 4) ? g_xTl : g_cTl;
    const int n0 = blockIdx.x*32, c0 = blockIdx.y*32;
    __shared__ float t[32][33];
    const int tx = threadIdx.x & 31, ty = threadIdx.x >> 5;
    #pragma unroll
    for (int r = 0; r < 4; ++r)
        t[ty + r*8][tx] = src[((size_t)b*Nn + n0 + ty + r*8)*Cc + c0 + tx];
    __syncthreads();
    #pragma unroll
    for (int r = 0; r < 4; ++r) {
        const float v = t[tx][ty + r*8];
        __nv_bfloat16 h = __float2bfloat16_rn(v);
        __nv_bfloat16 l = __float2bfloat16_rn(v - __bfloat162float(h));
        const size_t o = ((size_t)b*Cc + c0 + ty + r*8)*Nn + n0 + tx;
        dh[o] = h; dl[o] = l;
    }
}

__global__ void sreduce_kernel()
{
    const size_t i4 = ((size_t)blockIdx.x*256 + threadIdx.x)*4;
    const size_t stride = (size_t)Bb*Cc*Cc;
    float4 a = *(const float4*)&g_Gpart[i4];
    #pragma unroll
    for (int s = 1; s < SPL; ++s) {
        float4 p = *(const float4*)&g_Gpart[s*stride + i4];
        a.x += p.x; a.y += p.y; a.z += p.z; a.w += p.w;
    }
    split_store4(a, g_Gth, g_Gtl, i4);
}

// ---------------------------------------------------------------------------
// colsum (R10-proven structure)
// ---------------------------------------------------------------------------
__global__ void colsum_part_kernel(const float* __restrict__ x, const float* __restrict__ ctx)
{
    const int z = blockIdx.z;
    const int sid = z >> 3, chunk = z & 7;
    const float* src = sid ? ctx : x;
    const int b = blockIdx.y;
    const int c = blockIdx.x*128 + threadIdx.x;
    const float* p = src + (size_t)b*Nn*Cc + (size_t)chunk*(Nn/8)*Cc + c;
    float s = 0.f;
    #pragma unroll 8
    for (int n = 0; n < Nn/8; ++n) s += p[(size_t)n*Cc];
    g_cspart[sid][chunk][b][c] = s;
}

__global__ void colsum_red_kernel()
{
    const int sid = blockIdx.z;
    const int b = blockIdx.y;
    const int c = blockIdx.x*128 + threadIdx.x;
    float s = 0.f;
    #pragma unroll
    for (int k = 0; k < 8; ++k) s += g_cspart[sid][k][b][c];
    if (sid) g_sc[b][c] = s; else g_sx[b][c] = s;
}

// ---------------------------------------------------------------------------
// att: logits + rank-1 bias terms + softmax (R10-proven)
// ---------------------------------------------------------------------------
#define TSROW 68

__global__ __launch_bounds__(256)
void att_kernel(const float* __restrict__ Wq, const float* __restrict__ bq_,
                const float* __restrict__ Wk, const float* __restrict__ bk_,
                float* __restrict__ att_out)
{
    const int bh = blockIdx.x;
    const int b = bh >> 3, h = bh & 7, h64 = h * 64;

    __shared__ float Ts[64][TSROW];
    __shared__ float Wks[64][65];
    __shared__ float u[64], w[64];

    const int tid = threadIdx.x;
    const int d = tid >> 2, g = tid & 3;

    if (tid < 64) {
        const float* r = Wq + (size_t)(h64 + tid) * Cc;
        float a = 0.f;
        for (int c = 0; c < Cc; ++c) a = fmaf(r[c], g_sx[b][c], a);
        u[tid] = a;
    } else if (tid < 128) {
        const int e = tid - 64;
        const float* r = Wk + (size_t)(h64 + e) * Cc;
        float a = 0.f;
        for (int c = 0; c < Cc; ++c) a = fmaf(r[c], g_sc[b][c], a);
        w[e] = a;
    }

    float acc[16];
    #pragma unroll
    for (int j = 0; j < 16; ++j) acc[j] = 0.f;

    for (int k0 = 0; k0 < Cc; k0 += 64) {
        __syncthreads();
        for (int i = tid; i < 64*16; i += 256) {
            const int row = i >> 4, c4 = (i & 15) << 2;
            float4 tv = *(const float4*)&g_T[((size_t)b*Cc + h64 + row)*Cc + k0 + c4];
            *(float4*)&Ts[row][c4] = tv;
            float4 wv = *(const float4*)&Wk[(size_t)(h64 + row)*Cc + k0 + c4];
            Wks[c4+0][row] = wv.x; Wks[c4+1][row] = wv.y;
            Wks[c4+2][row] = wv.z; Wks[c4+3][row] = wv.w;
        }
        __syncthreads();
        #pragma unroll 16
        for (int k = 0; k < 64; ++k) {
            const float tv = Ts[d][k];
            #pragma unroll
            for (int j = 0; j < 16; ++j)
                acc[j] = fmaf(tv, Wks[k][g*16 + j], acc[j]);
        }
    }
    __syncthreads();

    const float bqd = bq_[h64 + d];
    const float ud  = u[d];
    float v[16];
    #pragma unroll
    for (int j = 0; j < 16; ++j) {
        const int e = g*16 + j;
        const float l = acc[j] + bqd * w[e] + bk_[h64 + e] * ud
                      + (float)Nn * bqd * bk_[h64 + e];
        v[j] = l * 0.125f;
    }

    float mx = v[0];
    #pragma unroll
    for (int j = 1; j < 16; ++j) mx = fmaxf(mx, v[j]);
    mx = fmaxf(mx, __shfl_xor_sync(0xffffffff, mx, 1));
    mx = fmaxf(mx, __shfl_xor_sync(0xffffffff, mx, 2));
    float sum = 0.f;
    #pragma unroll
    for (int j = 0; j < 16; ++j) { v[j] = expf(v[j] - mx); sum += v[j]; }
    sum += __shfl_xor_sync(0xffffffff, sum, 1);
    sum += __shfl_xor_sync(0xffffffff, sum, 2);
    const float inv = 1.f / sum;

    const size_t base = ((size_t)bh*64 + d)*64 + g*16;
    #pragma unroll
    for (int q = 0; q < 4; ++q) {
        float4 o;
        o.x = v[q*4+0]*inv; o.y = v[q*4+1]*inv;
        o.z = v[q*4+2]*inv; o.w = v[q*4+3]*inv;
        *(float4*)&g_att[base + q*4] = o;
        if (att_out) *(float4*)&att_out[base + q*4] = o;
    }
}

// ---------------------------------------------------------------------------
// buildM: M[b][cp][h64+e] = sum_d proj_w[cp][h64+d] att[b,h,d,e] -> fp32
// (R10 structure; only the store type changed)
// ---------------------------------------------------------------------------
__global__ __launch_bounds__(256)
void buildM_kernel(const float* __restrict__ proj_w)
{
    const int b   = blockIdx.x;
    const int cp0 = blockIdx.y * 64;
    __shared__ float atts[64][65];
    const int tid = threadIdx.x;

    for (int h = 0; h < Hh; ++h) {
        for (int i = tid; i < 64*64; i += 256) {
            const int d2 = i >> 6, e = i & 63;
            atts[d2][e] = g_att[(((size_t)(b*Hh + h)*64) + d2)*64 + e];
        }
        __syncthreads();
        for (int ww = tid; ww < 64*16; ww += 256) {
            const int cp = cp0 + (ww >> 4);
            const int e4 = (ww & 15) << 2;
            const float* pw = proj_w + (size_t)cp*Cc + h*64;
            float a0=0.f, a1=0.f, a2=0.f, a3=0.f;
            #pragma unroll 16
            for (int d2 = 0; d2 < 64; ++d2) {
                const float p = pw[d2];
                a0 = fmaf(p, atts[d2][e4+0], a0);
                a1 = fmaf(p, atts[d2][e4+1], a1);
                a2 = fmaf(p, atts[d2][e4+2], a2);
                a3 = fmaf(p, atts[d2][e4+3], a3);
            }
            float4 vv; vv.x=a0; vv.y=a1; vv.z=a2; vv.w=a3;
            *(float4*)&g_M[(((size_t)b*Cc + cp)*Cc) + h*64 + e4] = vv;
        }
        __syncthreads();
    }
}

// ---------------------------------------------------------------------------
// w2: W2[b][cp][c2] = sum_k M[b][cp][k] * Wv[k][c2]  (scalar, spill-proof)
// grid (1024, 1, Bb) x 256 thr -> one thread per output element.
// M row broadcast via L2; Wv reads coalesced across consecutive c2 threads.
// ---------------------------------------------------------------------------
__global__ void w2_kernel(const float* __restrict__ Wv)
{
    const int b   = blockIdx.z;
    const int idx = blockIdx.x*256 + threadIdx.x;   // 0 .. 262143
    const int cp  = idx >> 9;
    const int c2  = idx & 511;
    const float* m = g_M + ((size_t)b*Cc + cp)*Cc;
    float s = 0.f;
    for (int k = 0; k < Cc; ++k)
        s = fmaf(m[k], Wv[(size_t)k*Cc + c2], s);
    __nv_bfloat16 h = __float2bfloat16_rn(s);
    __nv_bfloat16 l = __float2bfloat16_rn(s - __bfloat162float(h));
    const size_t o = ((size_t)b*Cc + cp)*Cc + c2;
    g_W2h[o] = h;
    g_W2l[o] = l;
}

// b2[b][cp] = proj_b[cp] + sum_j M[b][cp][j] * bv[j]  (scalar, spill-proof)
__global__ void b2_kernel(const float* __restrict__ bv, const float* __restrict__ proj_b)
{
    const int b  = blockIdx.x;
    const int cp = threadIdx.x;   // 512
    const float* m = g_M + ((size_t)b*Cc + cp)*Cc;
    float s = proj_b[cp];
    for (int j = 0; j < Cc; ++j) s = fmaf(m[j], bv[j], s);
    g_b2[b*Cc + cp] = s;
}

// ---------------------------------------------------------------------------
extern "C" void kernel_launch(void* const* d_in, const int* in_sizes, int n_in,
                              void* d_out, int out_size)
{
    const float* x      = (const float*)d_in[0];
    const float* ctx    = (const float*)d_in[1];
    const float* Wq     = (const float*)d_in[2];
    const float* bq     = (const float*)d_in[3];
    const float* Wk     = (const float*)d_in[4];
    const float* bk     = (const float*)d_in[5];
    const float* Wv     = (const float*)d_in[6];
    const float* bv     = (const float*)d_in[7];
    const float* proj_w = (const float*)d_in[8];
    const float* proj_b = (const float*)d_in[9];
    float* out = (float*)d_out;

    float* att_out = (out_size >= OUT_ELEMS + ATT_ELEMS) ? (out + OUT_ELEMS) : nullptr;

    // launches 1-5 (ncu -s 5 -c 1 captures launch 6 = spart_tc)
    conv_ctx_kernel   <<<16384, 256>>>(ctx);
    conv_wq_kernel    <<<256, 256>>>(Wq);
    convT_kernel      <<<dim3(Nn/32, Cc/32, 8), 256>>>(x, ctx);
    colsum_part_kernel<<<dim3(Cc/128, Bb, 16), 128>>>(x, ctx);
    colsum_red_kernel <<<dim3(Cc/128, Bb, 2), 128>>>();

    spart_tc <<<dim3(16, Bb, SPL), 256>>>();          // launch 6: profiled
    sreduce_kernel<<<1024, 256>>>();
    T_tc     <<<dim3(Cc/128, Cc/128, Bb), 256>>>();
    att_kernel<<<Bb*Hh, 256>>>(Wq, bq, Wk, bk, att_out);
    buildM_kernel<<<dim3(Bb, Cc/64), 256>>>(proj_w);
    w2_kernel<<<dim3(1024, 1, Bb), 256>>>(Wv);
    b2_kernel<<<Bb, 512>>>(bv, proj_b);
    out_tc   <<<dim3(Bb*Nn/128, Cc/128), 256>>>(out);
}

// round 15
// speedup vs baseline: 1.3276x; 1.3276x over previous
#include <cuda_runtime.h>
#include <cuda_fp16.h>
#include <cstdint>
#include <math.h>

#define Bb 4
#define Nn 8192
#define Cc 512
#define Hh 8
#define Dd 64
#define SPL 4
#define OUT_ELEMS (Bb*Nn*Cc)
#define ATT_ELEMS (Bb*Hh*Dd*Dd)

// ---------------------------------------------------------------------------
// Static scratch
// ---------------------------------------------------------------------------
__device__ float g_Gpart[SPL*Bb*Cc*Cc];     // split-K partials of Gt
__device__ float g_T[Bb*Cc*Cc];
__device__ float g_att[ATT_ELEMS];
__device__ float g_M[Bb*Cc*Cc];             // fused proj*att (fp32, for b2)
__device__ float g_W2f[Bb*Cc*Cc];           // W2 fp32
__device__ float g_b2[Bb*Cc];
__device__ float g_sx[Bb][Cc];
__device__ float g_sc[Bb][Cc];
__device__ float g_cspart[2][32][Bb][Cc];

__device__ __half g_ch[Bb*Nn*Cc];                       // ctx (K=c major, single)
__device__ __half g_cT[Bb*Cc*Nn];                       // ctx^T (single, A of spart)
__device__ __half g_xTh[Bb*Cc*Nn], g_xTl[Bb*Cc*Nn];    // x^T h/l (B of spart)
__device__ __half g_Gth[Bb*Cc*Cc], g_Gtl[Bb*Cc*Cc];    // Gt h/l
__device__ __half g_Wq[Cc*Cc];                          // Wq single
__device__ __half g_M16[Bb*Cc*Cc];                      // M fp16 (A of w2)
__device__ __half g_WvTh[Cc*Cc], g_WvTl[Cc*Cc];        // Wv^T h/l
__device__ __half g_W2h[Bb*Cc*Cc], g_W2l[Bb*Cc*Cc];    // W2 h/l

// ---------------------------------------------------------------------------
// mma.sync m16n8k16 f16 + ldmatrix
// ---------------------------------------------------------------------------
__device__ __forceinline__ void mma16816(float* c, const uint32_t* a, const uint32_t* b)
{
    asm volatile(
        "mma.sync.aligned.m16n8k16.row.col.f32.f16.f16.f32 "
        "{%0,%1,%2,%3}, {%4,%5,%6,%7}, {%8,%9}, {%0,%1,%2,%3};"
        : "+f"(c[0]), "+f"(c[1]), "+f"(c[2]), "+f"(c[3])
        : "r"(a[0]), "r"(a[1]), "r"(a[2]), "r"(a[3]), "r"(b[0]), "r"(b[1]));
}
__device__ __forceinline__ void ldsm_x4(uint32_t* r, const __half* p)
{
    uint32_t addr = (uint32_t)__cvta_generic_to_shared(p);
    asm volatile("ldmatrix.sync.aligned.m8n8.x4.shared.b16 {%0,%1,%2,%3}, [%4];"
                 : "=r"(r[0]), "=r"(r[1]), "=r"(r[2]), "=r"(r[3]) : "r"(addr));
}
// pack 4 floats -> 4 halfs (uint2), plus residual low halfs
__device__ __forceinline__ void f4_to_h16(float4 v, uint2& h)
{
    __half h0 = __float2half_rn(v.x), h1 = __float2half_rn(v.y);
    __half h2 = __float2half_rn(v.z), h3 = __float2half_rn(v.w);
    h.x = (uint32_t)__half_as_ushort(h0) | ((uint32_t)__half_as_ushort(h1) << 16);
    h.y = (uint32_t)__half_as_ushort(h2) | ((uint32_t)__half_as_ushort(h3) << 16);
}
__device__ __forceinline__ void f4_to_hl16(float4 v, uint2& h, uint2& l)
{
    __half h0 = __float2half_rn(v.x), h1 = __float2half_rn(v.y);
    __half h2 = __float2half_rn(v.z), h3 = __float2half_rn(v.w);
    __half l0 = __float2half_rn(v.x - __half2float(h0));
    __half l1 = __float2half_rn(v.y - __half2float(h1));
    __half l2 = __float2half_rn(v.z - __half2float(h2));
    __half l3 = __float2half_rn(v.w - __half2float(h3));
    h.x = (uint32_t)__half_as_ushort(h0) | ((uint32_t)__half_as_ushort(h1) << 16);
    h.y = (uint32_t)__half_as_ushort(h2) | ((uint32_t)__half_as_ushort(h3) << 16);
    l.x = (uint32_t)__half_as_ushort(l0) | ((uint32_t)__half_as_ushort(l1) << 16);
    l.y = (uint32_t)__half_as_ushort(l2) | ((uint32_t)__half_as_ushort(l3) << 16);
}

// ---------------------------------------------------------------------------
// GEMM tile: D[128x128] = sum_k A[128,K] B[128,K]^T.
// fp16 asymmetric split-2: A single fp16, B = Bh + Bl. 2 MMAs per target.
// 256 thr, 8 warps 32x64, Kc=32, 30KB static smem, register prefetch,
// ldmatrix frag loads, fp32 epilogue (+bias). (R14-proven skeleton.)
// ---------------------------------------------------------------------------
#define SK 40
#define TILE_ELEMS (128*SK)

__device__ void tc_gemm_tile(
    const __half* __restrict__ A, int lda,
    const __half* __restrict__ Bh, const __half* __restrict__ Bl, int ldb,
    int K, int row0, int col0,
    const float* __restrict__ bias,
    float* __restrict__ outF, int ldo)
{
    __shared__ __half sm[3*TILE_ELEMS];   // 30720 B static

    const int tid  = threadIdx.x;
    const int lane = tid & 31;
    const int wid  = tid >> 5;
    const int wm   = wid >> 1;
    const int wn   = wid & 1;
    const int gr   = lane >> 2;
    const int kp   = (lane & 3) << 1;
    const int lrow = lane & 15;
    const int lkof = (lane >> 4) * 8;

    const int prow = tid >> 1;
    const int pc0  = (tid & 1) * 16;

    float acc[64];
    #pragma unroll
    for (int i = 0; i < 64; ++i) acc[i] = 0.f;

    uint2 pfa[4];
    uint2 pfb[2][4];

    #pragma unroll
    for (int i = 0; i < 4; ++i) {
        pfa[i]    = *(const uint2*)(A  + (size_t)(row0+prow)*lda + pc0 + i*4);
        pfb[0][i] = *(const uint2*)(Bh + (size_t)(col0+prow)*ldb + pc0 + i*4);
        pfb[1][i] = *(const uint2*)(Bl + (size_t)(col0+prow)*ldb + pc0 + i*4);
    }

    const int nch = K / 32;
    for (int c = 0; c < nch; ++c) {
        __syncthreads();
        #pragma unroll
        for (int i = 0; i < 4; ++i) {
            *(uint2*)(sm + 0*TILE_ELEMS + prow*SK + pc0 + i*4) = pfa[i];
            *(uint2*)(sm + 1*TILE_ELEMS + prow*SK + pc0 + i*4) = pfb[0][i];
            *(uint2*)(sm + 2*TILE_ELEMS + prow*SK + pc0 + i*4) = pfb[1][i];
        }
        __syncthreads();

        if (c + 1 < nch) {
            const int k0 = (c + 1) * 32;
            #pragma unroll
            for (int i = 0; i < 4; ++i) {
                pfa[i]    = *(const uint2*)(A  + (size_t)(row0+prow)*lda + k0 + pc0 + i*4);
                pfb[0][i] = *(const uint2*)(Bh + (size_t)(col0+prow)*ldb + k0 + pc0 + i*4);
                pfb[1][i] = *(const uint2*)(Bl + (size_t)(col0+prow)*ldb + k0 + pc0 + i*4);
            }
        }

        const __half* sA  = sm + 0*TILE_ELEMS;
        const __half* sBh = sm + 1*TILE_ELEMS;
        const __half* sBl = sm + 2*TILE_ELEMS;

        #pragma unroll
        for (int k16 = 0; k16 < 32; k16 += 16) {
            uint32_t ah[2][4];
            #pragma unroll
            for (int mt = 0; mt < 2; ++mt) {
                const int m0 = wm*32 + mt*16;
                ldsm_x4(ah[mt], sA + (m0 + lrow)*SK + k16 + lkof);
            }
            #pragma unroll
            for (int nt2 = 0; nt2 < 4; ++nt2) {
                const int n0 = wn*64 + nt2*16;
                uint32_t bh4[4], bl4[4];
                ldsm_x4(bh4, sBh + (n0 + lrow)*SK + k16 + lkof);
                ldsm_x4(bl4, sBl + (n0 + lrow)*SK + k16 + lkof);
                uint32_t bhE[2] = {bh4[0], bh4[2]}, bhO[2] = {bh4[1], bh4[3]};
                uint32_t blE[2] = {bl4[0], bl4[2]}, blO[2] = {bl4[1], bl4[3]};
                #pragma unroll
                for (int mt = 0; mt < 2; ++mt) {
                    float* ccE = &acc[(mt*8 + 2*nt2    )*4];
                    float* ccO = &acc[(mt*8 + 2*nt2 + 1)*4];
                    mma16816(ccE, ah[mt], bhE);
                    mma16816(ccE, ah[mt], blE);
                    mma16816(ccO, ah[mt], bhO);
                    mma16816(ccO, ah[mt], blO);
                }
            }
        }
    }

    #pragma unroll
    for (int mt = 0; mt < 2; ++mt) {
        const int r0 = row0 + wm*32 + mt*16 + gr;
        #pragma unroll
        for (int nt = 0; nt < 8; ++nt) {
            const int col = col0 + wn*64 + nt*8 + kp;
            const float* cc = &acc[(mt*8 + nt)*4];
            float b0 = bias ? bias[col]     : 0.f;
            float b1 = bias ? bias[col + 1] : 0.f;
            *(float2*)(outF + (size_t)r0*ldo + col)     = make_float2(cc[0] + b0, cc[1] + b1);
            *(float2*)(outF + (size_t)(r0+8)*ldo + col) = make_float2(cc[2] + b0, cc[3] + b1);
        }
    }
}

// ---------------------------------------------------------------------------
// GEMM wrapper kernels
// ---------------------------------------------------------------------------
__global__ __launch_bounds__(256)
void spart_tc()   // Gt[c2][c1] = sum_n ctx[n,c2] x[n,c1], split-K over n
{
    const int t = blockIdx.x, b = blockIdx.y, s = blockIdx.z;
    const size_t tb = (size_t)b*Cc*Nn + (size_t)s*(Nn/SPL);
    tc_gemm_tile(g_cT + tb, Nn,
                 g_xTh + tb, g_xTl + tb, Nn,
                 Nn/SPL, (t >> 2)*128, (t & 3)*128,
                 nullptr,
                 g_Gpart + ((size_t)s*Bb + b)*Cc*Cc, Cc);
}

__global__ __launch_bounds__(256)
void T_tc()   // T[b] = Wq @ Gt[b]^T
{
    const int b = blockIdx.z;
    tc_gemm_tile(g_Wq, Cc,
                 g_Gth + (size_t)b*Cc*Cc, g_Gtl + (size_t)b*Cc*Cc, Cc,
                 Cc, blockIdx.x*128, blockIdx.y*128,
                 nullptr, g_T + (size_t)b*Cc*Cc, Cc);
}

__global__ __launch_bounds__(256)
void w2_tc()  // W2[b] = M[b] @ WvT^T  (i.e. M @ Wv)
{
    const int b = blockIdx.z;
    tc_gemm_tile(g_M16 + (size_t)b*Cc*Cc, Cc,
                 g_WvTh, g_WvTl, Cc,
                 Cc, blockIdx.x*128, blockIdx.y*128,
                 nullptr, g_W2f + (size_t)b*Cc*Cc, Cc);
}

__global__ __launch_bounds__(256)
void out_tc(float* __restrict__ out)   // out[b] = ctx[b] @ W2[b]^T + b2[b]
{
    const int row0 = blockIdx.x*128;
    const int b = row0 >> 13;
    tc_gemm_tile(g_ch, Cc,
                 g_W2h + (size_t)b*Cc*Cc, g_W2l + (size_t)b*Cc*Cc, Cc,
                 Cc, row0, blockIdx.y*128,
                 g_b2 + (size_t)b*Cc, out, Cc);
}

// ---------------------------------------------------------------------------
// Conversion kernels
// ---------------------------------------------------------------------------
__global__ void conv_ctx_kernel(const float* __restrict__ ctx)
{
    const size_t i = ((size_t)blockIdx.x*256 + threadIdx.x)*4;
    uint2 h;
    f4_to_h16(*(const float4*)(ctx + i), h);
    *(uint2*)(g_ch + i) = h;
}

__global__ void conv_wq_kernel(const float* __restrict__ Wq)
{
    const size_t i = ((size_t)blockIdx.x*256 + threadIdx.x)*4;
    uint2 h;
    f4_to_h16(*(const float4*)(Wq + i), h);
    *(uint2*)(g_Wq + i) = h;
}

// x -> xT h/l ; ctx -> cT single
__global__ void convT_kernel(const float* __restrict__ x, const float* __restrict__ ctx)
{
    const int z = blockIdx.z;
    const int b = z & 3;
    const bool isx = (z < 4);
    const float* src = isx ? x : ctx;
    const int n0 = blockIdx.x*32, c0 = blockIdx.y*32;
    __shared__ float t[32][33];
    const int tx = threadIdx.x & 31, ty = threadIdx.x >> 5;
    #pragma unroll
    for (int r = 0; r < 4; ++r)
        t[ty + r*8][tx] = src[((size_t)b*Nn + n0 + ty + r*8)*Cc + c0 + tx];
    __syncthreads();
    #pragma unroll
    for (int r = 0; r < 4; ++r) {
        const float v = t[tx][ty + r*8];
        const __half h = __float2half_rn(v);
        const size_t o = ((size_t)b*Cc + c0 + ty + r*8)*Nn + n0 + tx;
        if (isx) {
            g_xTh[o] = h;
            g_xTl[o] = __float2half_rn(v - __half2float(h));
        } else {
            g_cT[o] = h;
        }
    }
}

// Wv[k][c2] -> WvT[c2][k] h/l  (512x512)
__global__ void convT_wv_kernel(const float* __restrict__ Wv)
{
    const int k0 = blockIdx.x*32, c0 = blockIdx.y*32;
    __shared__ float t[32][33];
    const int tx = threadIdx.x & 31, ty = threadIdx.x >> 5;
    #pragma unroll
    for (int r = 0; r < 4; ++r)
        t[ty + r*8][tx] = Wv[(size_t)(k0 + ty + r*8)*Cc + c0 + tx];
    __syncthreads();
    #pragma unroll
    for (int r = 0; r < 4; ++r) {
        const float v = t[tx][ty + r*8];   // Wv[k0+tx][c0+ty+r*8]
        const __half h = __float2half_rn(v);
        const size_t o = (size_t)(c0 + ty + r*8)*Cc + k0 + tx;
        g_WvTh[o] = h;
        g_WvTl[o] = __float2half_rn(v - __half2float(h));
    }
}

__global__ void sreduce_kernel()
{
    const size_t i4 = ((size_t)blockIdx.x*256 + threadIdx.x)*4;
    const size_t stride = (size_t)Bb*Cc*Cc;
    float4 a = *(const float4*)&g_Gpart[i4];
    #pragma unroll
    for (int s = 1; s < SPL; ++s) {
        float4 p = *(const float4*)&g_Gpart[s*stride + i4];
        a.x += p.x; a.y += p.y; a.z += p.z; a.w += p.w;
    }
    uint2 h, l;
    f4_to_hl16(a, h, l);
    *(uint2*)(g_Gth + i4) = h;
    *(uint2*)(g_Gtl + i4) = l;
}

// W2 fp32 -> h/l fp16
__global__ void conv_w2_kernel()
{
    const size_t i = ((size_t)blockIdx.x*256 + threadIdx.x)*4;
    uint2 h, l;
    f4_to_hl16(*(const float4*)(g_W2f + i), h, l);
    *(uint2*)(g_W2h + i) = h;
    *(uint2*)(g_W2l + i) = l;
}

// ---------------------------------------------------------------------------
// colsum (R14-proven scalar body; z widened to 64 for occupancy)
// ---------------------------------------------------------------------------
__global__ void colsum_part_kernel(const float* __restrict__ x, const float* __restrict__ ctx)
{
    const int z = blockIdx.z;
    const int sid = z >> 5, chunk = z & 31;
    const float* src = sid ? ctx : x;
    const int b = blockIdx.y;
    const int c = blockIdx.x*128 + threadIdx.x;
    const float* p = src + (size_t)b*Nn*Cc + (size_t)chunk*(Nn/32)*Cc + c;
    float s = 0.f;
    #pragma unroll 8
    for (int n = 0; n < Nn/32; ++n) s += p[(size_t)n*Cc];
    g_cspart[sid][chunk][b][c] = s;
}

__global__ void colsum_red_kernel()
{
    const int sid = blockIdx.z;
    const int b = blockIdx.y;
    const int c = blockIdx.x*128 + threadIdx.x;
    float s = 0.f;
    #pragma unroll
    for (int k = 0; k < 32; ++k) s += g_cspart[sid][k][b][c];
    if (sid) g_sc[b][c] = s; else g_sx[b][c] = s;
}

// ---------------------------------------------------------------------------
// att: logits + rank-1 bias terms + softmax (R14-proven, fp32)
// ---------------------------------------------------------------------------
#define TSROW 68

__global__ __launch_bounds__(256)
void att_kernel(const float* __restrict__ Wq, const float* __restrict__ bq_,
                const float* __restrict__ Wk, const float* __restrict__ bk_,
                float* __restrict__ att_out)
{
    const int bh = blockIdx.x;
    const int b = bh >> 3, h = bh & 7, h64 = h * 64;

    __shared__ float Ts[64][TSROW];
    __shared__ float Wks[64][65];
    __shared__ float u[64], w[64];

    const int tid = threadIdx.x;
    const int d = tid >> 2, g = tid & 3;

    if (tid < 64) {
        const float* r = Wq + (size_t)(h64 + tid) * Cc;
        float a = 0.f;
        for (int c = 0; c < Cc; ++c) a = fmaf(r[c], g_sx[b][c], a);
        u[tid] = a;
    } else if (tid < 128) {
        const int e = tid - 64;
        const float* r = Wk + (size_t)(h64 + e) * Cc;
        float a = 0.f;
        for (int c = 0; c < Cc; ++c) a = fmaf(r[c], g_sc[b][c], a);
        w[e] = a;
    }

    float acc[16];
    #pragma unroll
    for (int j = 0; j < 16; ++j) acc[j] = 0.f;

    for (int k0 = 0; k0 < Cc; k0 += 64) {
        __syncthreads();
        for (int i = tid; i < 64*16; i += 256) {
            const int row = i >> 4, c4 = (i & 15) << 2;
            float4 tv = *(const float4*)&g_T[((size_t)b*Cc + h64 + row)*Cc + k0 + c4];
            *(float4*)&Ts[row][c4] = tv;
            float4 wv = *(const float4*)&Wk[(size_t)(h64 + row)*Cc + k0 + c4];
            Wks[c4+0][row] = wv.x; Wks[c4+1][row] = wv.y;
            Wks[c4+2][row] = wv.z; Wks[c4+3][row] = wv.w;
        }
        __syncthreads();
        #pragma unroll 16
        for (int k = 0; k < 64; ++k) {
            const float tv = Ts[d][k];
            #pragma unroll
            for (int j = 0; j < 16; ++j)
                acc[j] = fmaf(tv, Wks[k][g*16 + j], acc[j]);
        }
    }
    __syncthreads();

    const float bqd = bq_[h64 + d];
    const float ud  = u[d];
    float v[16];
    #pragma unroll
    for (int j = 0; j < 16; ++j) {
        const int e = g*16 + j;
        const float l = acc[j] + bqd * w[e] + bk_[h64 + e] * ud
                      + (float)Nn * bqd * bk_[h64 + e];
        v[j] = l * 0.125f;
    }

    float mx = v[0];
    #pragma unroll
    for (int j = 1; j < 16; ++j) mx = fmaxf(mx, v[j]);
    mx = fmaxf(mx, __shfl_xor_sync(0xffffffff, mx, 1));
    mx = fmaxf(mx, __shfl_xor_sync(0xffffffff, mx, 2));
    float sum = 0.f;
    #pragma unroll
    for (int j = 0; j < 16; ++j) { v[j] = expf(v[j] - mx); sum += v[j]; }
    sum += __shfl_xor_sync(0xffffffff, sum, 1);
    sum += __shfl_xor_sync(0xffffffff, sum, 2);
    const float inv = 1.f / sum;

    const size_t base = ((size_t)bh*64 + d)*64 + g*16;
    #pragma unroll
    for (int q = 0; q < 4; ++q) {
        float4 o;
        o.x = v[q*4+0]*inv; o.y = v[q*4+1]*inv;
        o.z = v[q*4+2]*inv; o.w = v[q*4+3]*inv;
        *(float4*)&g_att[base + q*4] = o;
        if (att_out) *(float4*)&att_out[base + q*4] = o;
    }
}

// ---------------------------------------------------------------------------
// buildM: M[b][cp][h64+e] = sum_d proj_w[cp][h64+d] att[b,h,d,e]
// writes fp32 (for b2) + fp16 (for w2_tc)
// ---------------------------------------------------------------------------
__global__ __launch_bounds__(256)
void buildM_kernel(const float* __restrict__ proj_w)
{
    const int b   = blockIdx.x;
    const int cp0 = blockIdx.y * 64;
    __shared__ float atts[64][65];
    const int tid = threadIdx.x;

    for (int h = 0; h < Hh; ++h) {
        for (int i = tid; i < 64*64; i += 256) {
            const int d2 = i >> 6, e = i & 63;
            atts[d2][e] = g_att[(((size_t)(b*Hh + h)*64) + d2)*64 + e];
        }
        __syncthreads();
        for (int ww = tid; ww < 64*16; ww += 256) {
            const int cp = cp0 + (ww >> 4);
            const int e4 = (ww & 15) << 2;
            const float* pw = proj_w + (size_t)cp*Cc + h*64;
            float a0=0.f, a1=0.f, a2=0.f, a3=0.f;
            #pragma unroll 16
            for (int d2 = 0; d2 < 64; ++d2) {
                const float p = pw[d2];
                a0 = fmaf(p, atts[d2][e4+0], a0);
                a1 = fmaf(p, atts[d2][e4+1], a1);
                a2 = fmaf(p, atts[d2][e4+2], a2);
                a3 = fmaf(p, atts[d2][e4+3], a3);
            }
            const size_t o = (((size_t)b*Cc + cp)*Cc) + h*64 + e4;
            float4 vv; vv.x=a0; vv.y=a1; vv.z=a2; vv.w=a3;
            *(float4*)&g_M[o] = vv;
            uint2 hh;
            f4_to_h16(vv, hh);
            *(uint2*)(g_M16 + o) = hh;
        }
        __syncthreads();
    }
}

// b2[b][cp] = proj_b[cp] + sum_j M[b][cp][j] * bv[j]  (scalar, R14-proven)
__global__ void b2_kernel(const float* __restrict__ bv, const float* __restrict__ proj_b)
{
    const int b  = blockIdx.x;
    const int cp = threadIdx.x;   // 512
    const float* m = g_M + ((size_t)b*Cc + cp)*Cc;
    float s = proj_b[cp];
    for (int j = 0; j < Cc; ++j) s = fmaf(m[j], bv[j], s);
    g_b2[b*Cc + cp] = s;
}

// ---------------------------------------------------------------------------
extern "C" void kernel_launch(void* const* d_in, const int* in_sizes, int n_in,
                              void* d_out, int out_size)
{
    const float* x      = (const float*)d_in[0];
    const float* ctx    = (const float*)d_in[1];
    const float* Wq     = (const float*)d_in[2];
    const float* bq     = (const float*)d_in[3];
    const float* Wk     = (const float*)d_in[4];
    const float* bk     = (const float*)d_in[5];
    const float* Wv     = (const float*)d_in[6];
    const float* bv     = (const float*)d_in[7];
    const float* proj_w = (const float*)d_in[8];
    const float* proj_b = (const float*)d_in[9];
    float* out = (float*)d_out;

    float* att_out = (out_size >= OUT_ELEMS + ATT_ELEMS) ? (out + OUT_ELEMS) : nullptr;

    convT_kernel      <<<dim3(Nn/32, Cc/32, 8), 256>>>(x, ctx);   // 1
    conv_ctx_kernel   <<<16384, 256>>>(ctx);                      // 2
    conv_wq_kernel    <<<256, 256>>>(Wq);                         // 3
    spart_tc          <<<dim3(16, Bb, SPL), 256>>>();             // 4 (profiled?)
    colsum_part_kernel<<<dim3(Cc/128, Bb, 64), 128>>>(x, ctx);    // 5
    colsum_red_kernel <<<dim3(Cc/128, Bb, 2), 128>>>();           // 6
    convT_wv_kernel   <<<dim3(16, 16), 256>>>(Wv);                // 7
    sreduce_kernel    <<<1024, 256>>>();                          // 8
    T_tc              <<<dim3(Cc/128, Cc/128, Bb), 256>>>();      // 9
    att_kernel        <<<Bb*Hh, 256>>>(Wq, bq, Wk, bk, att_out);  // 10
    buildM_kernel     <<<dim3(Bb, Cc/64), 256>>>(proj_w);         // 11
    w2_tc             <<<dim3(Cc/128, Cc/128, Bb), 256>>>();      // 12
    conv_w2_kernel    <<<1024, 256>>>();                          // 13
    b2_kernel         <<<Bb, 512>>>(bv, proj_b);                  // 14
    out_tc            <<<dim3(Bb*Nn/128, Cc/128), 256>>>(out);    // 15
}

// round 16
// speedup vs baseline: 1.5008x; 1.1305x over previous
#include <cuda_runtime.h>
#include <cuda_fp16.h>
#include <cstdint>
#include <math.h>

#define Bb 4
#define Nn 8192
#define Cc 512
#define Hh 8
#define Dd 64
#define SPL 4
#define OUT_ELEMS (Bb*Nn*Cc)
#define ATT_ELEMS (Bb*Hh*Dd*Dd)

// ---------------------------------------------------------------------------
// Static scratch
// ---------------------------------------------------------------------------
__device__ float g_Gpart[SPL*Bb*Cc*Cc];
__device__ float g_T[Bb*Cc*Cc];
__device__ float g_att[ATT_ELEMS];
__device__ float g_M[Bb*Cc*Cc];
__device__ float g_W2f[Bb*Cc*Cc];
__device__ float g_b2[Bb*Cc];
__device__ float g_sx[Bb][Cc];
__device__ float g_sc[Bb][Cc];
__device__ float g_cspart[2][32][Bb][Cc];

__device__ __half g_ch[Bb*Nn*Cc];                       // ctx (K=c major, single)
__device__ __half g_cT[Bb*Cc*Nn];                       // ctx^T (single)
__device__ __half g_xTh[Bb*Cc*Nn], g_xTl[Bb*Cc*Nn];    // x^T h/l
__device__ __half g_Gth[Bb*Cc*Cc], g_Gtl[Bb*Cc*Cc];    // Gt h/l
__device__ __half g_Wq[Cc*Cc];
__device__ __half g_M16[Bb*Cc*Cc];
__device__ __half g_WvTh[Cc*Cc], g_WvTl[Cc*Cc];
__device__ __half g_W2h[Bb*Cc*Cc], g_W2l[Bb*Cc*Cc];

// ---------------------------------------------------------------------------
// mma.sync m16n8k16 f16 + ldmatrix + cp.async
// ---------------------------------------------------------------------------
__device__ __forceinline__ void mma16816(float* c, const uint32_t* a, const uint32_t* b)
{
    asm volatile(
        "mma.sync.aligned.m16n8k16.row.col.f32.f16.f16.f32 "
        "{%0,%1,%2,%3}, {%4,%5,%6,%7}, {%8,%9}, {%0,%1,%2,%3};"
        : "+f"(c[0]), "+f"(c[1]), "+f"(c[2]), "+f"(c[3])
        : "r"(a[0]), "r"(a[1]), "r"(a[2]), "r"(a[3]), "r"(b[0]), "r"(b[1]));
}
__device__ __forceinline__ void ldsm_x4(uint32_t* r, const __half* p)
{
    uint32_t addr = (uint32_t)__cvta_generic_to_shared(p);
    asm volatile("ldmatrix.sync.aligned.m8n8.x4.shared.b16 {%0,%1,%2,%3}, [%4];"
                 : "=r"(r[0]), "=r"(r[1]), "=r"(r[2]), "=r"(r[3]) : "r"(addr));
}
__device__ __forceinline__ void cp16(const __half* smem_dst, const __half* gmem_src)
{
    uint32_t d = (uint32_t)__cvta_generic_to_shared(smem_dst);
    asm volatile("cp.async.cg.shared.global [%0], [%1], 16;" :: "r"(d), "l"(gmem_src));
}
__device__ __forceinline__ void f4_to_h16(float4 v, uint2& h)
{
    __half h0 = __float2half_rn(v.x), h1 = __float2half_rn(v.y);
    __half h2 = __float2half_rn(v.z), h3 = __float2half_rn(v.w);
    h.x = (uint32_t)__half_as_ushort(h0) | ((uint32_t)__half_as_ushort(h1) << 16);
    h.y = (uint32_t)__half_as_ushort(h2) | ((uint32_t)__half_as_ushort(h3) << 16);
}
__device__ __forceinline__ void f4_to_hl16(float4 v, uint2& h, uint2& l)
{
    __half h0 = __float2half_rn(v.x), h1 = __float2half_rn(v.y);
    __half h2 = __float2half_rn(v.z), h3 = __float2half_rn(v.w);
    __half l0 = __float2half_rn(v.x - __half2float(h0));
    __half l1 = __float2half_rn(v.y - __half2float(h1));
    __half l2 = __float2half_rn(v.z - __half2float(h2));
    __half l3 = __float2half_rn(v.w - __half2float(h3));
    h.x = (uint32_t)__half_as_ushort(h0) | ((uint32_t)__half_as_ushort(h1) << 16);
    h.y = (uint32_t)__half_as_ushort(h2) | ((uint32_t)__half_as_ushort(h3) << 16);
    l.x = (uint32_t)__half_as_ushort(l0) | ((uint32_t)__half_as_ushort(l1) << 16);
    l.y = (uint32_t)__half_as_ushort(l2) | ((uint32_t)__half_as_ushort(l3) << 16);
}

// ---------------------------------------------------------------------------
// GEMM tile: D[128x128] = sum_k A[128,K] B[128,K]^T.
// fp16 asymmetric split-2 (A single, B = Bh+Bl). cp.async double-buffered:
// Kc=16, SK=24 (conflict-free), 2x3 tiles = 36KB static smem, 1 sync/chunk.
// 256 thr, 8 warps 32x64, fp32 epilogue (+bias).
// ---------------------------------------------------------------------------
#define SK 24
#define TILE_ELEMS (128*SK)    // 3072 halfs = 6144 B

__device__ void tc_gemm_tile(
    const __half* __restrict__ A, int lda,
    const __half* __restrict__ Bh, const __half* __restrict__ Bl, int ldb,
    int K, int row0, int col0,
    const float* __restrict__ bias,
    float* __restrict__ outF, int ldo)
{
    __shared__ __half sm[2][3*TILE_ELEMS];   // 36864 B static

    const int tid  = threadIdx.x;
    const int lane = tid & 31;
    const int wid  = tid >> 5;
    const int wm   = wid >> 1;
    const int wn   = wid & 1;
    const int gr   = lane >> 2;
    const int kp   = (lane & 3) << 1;
    const int lrow = lane & 15;
    const int lkof = (lane >> 4) * 8;

    // copy assignment: thread t -> row t>>1, 16B segment t&1 (per tensor)
    const int crow = tid >> 1;
    const int cseg = (tid & 1) * 8;

    const __half* srcA  = A  + (size_t)(row0 + crow)*lda + cseg;
    const __half* srcBh = Bh + (size_t)(col0 + crow)*ldb + cseg;
    const __half* srcBl = Bl + (size_t)(col0 + crow)*ldb + cseg;
    const int dstoff = crow*SK + cseg;

    float acc[64];
    #pragma unroll
    for (int i = 0; i < 64; ++i) acc[i] = 0.f;

    const int nch = K / 16;

    // prologue: chunk 0 -> buf 0
    cp16(&sm[0][0*TILE_ELEMS + dstoff], srcA);
    cp16(&sm[0][1*TILE_ELEMS + dstoff], srcBh);
    cp16(&sm[0][2*TILE_ELEMS + dstoff], srcBl);
    asm volatile("cp.async.commit_group;" ::: "memory");
    asm volatile("cp.async.wait_group 0;" ::: "memory");
    __syncthreads();

    for (int c = 0; c < nch; ++c) {
        const int buf = c & 1;
        if (c + 1 < nch) {
            const int k0 = (c + 1) * 16;
            const int nb = (c + 1) & 1;
            cp16(&sm[nb][0*TILE_ELEMS + dstoff], srcA  + k0);
            cp16(&sm[nb][1*TILE_ELEMS + dstoff], srcBh + k0);
            cp16(&sm[nb][2*TILE_ELEMS + dstoff], srcBl + k0);
            asm volatile("cp.async.commit_group;" ::: "memory");
        }

        const __half* sA  = &sm[buf][0*TILE_ELEMS];
        const __half* sBh = &sm[buf][1*TILE_ELEMS];
        const __half* sBl = &sm[buf][2*TILE_ELEMS];

        uint32_t ah[2][4];
        #pragma unroll
        for (int mt = 0; mt < 2; ++mt) {
            const int m0 = wm*32 + mt*16;
            ldsm_x4(ah[mt], sA + (m0 + lrow)*SK + lkof);
        }
        #pragma unroll
        for (int nt2 = 0; nt2 < 4; ++nt2) {
            const int n0 = wn*64 + nt2*16;
            uint32_t bh4[4], bl4[4];
            ldsm_x4(bh4, sBh + (n0 + lrow)*SK + lkof);
            ldsm_x4(bl4, sBl + (n0 + lrow)*SK + lkof);
            uint32_t bhE[2] = {bh4[0], bh4[2]}, bhO[2] = {bh4[1], bh4[3]};
            uint32_t blE[2] = {bl4[0], bl4[2]}, blO[2] = {bl4[1], bl4[3]};
            #pragma unroll
            for (int mt = 0; mt < 2; ++mt) {
                float* ccE = &acc[(mt*8 + 2*nt2    )*4];
                float* ccO = &acc[(mt*8 + 2*nt2 + 1)*4];
                mma16816(ccE, ah[mt], bhE);
                mma16816(ccE, ah[mt], blE);
                mma16816(ccO, ah[mt], bhO);
                mma16816(ccO, ah[mt], blO);
            }
        }

        asm volatile("cp.async.wait_group 0;" ::: "memory");
        __syncthreads();
    }

    #pragma unroll
    for (int mt = 0; mt < 2; ++mt) {
        const int r0 = row0 + wm*32 + mt*16 + gr;
        #pragma unroll
        for (int nt = 0; nt < 8; ++nt) {
            const int col = col0 + wn*64 + nt*8 + kp;
            const float* cc = &acc[(mt*8 + nt)*4];
            float b0 = bias ? bias[col]     : 0.f;
            float b1 = bias ? bias[col + 1] : 0.f;
            *(float2*)(outF + (size_t)r0*ldo + col)     = make_float2(cc[0] + b0, cc[1] + b1);
            *(float2*)(outF + (size_t)(r0+8)*ldo + col) = make_float2(cc[2] + b0, cc[3] + b1);
        }
    }
}

// ---------------------------------------------------------------------------
// GEMM wrapper kernels
// ---------------------------------------------------------------------------
__global__ __launch_bounds__(256)
void spart_tc()
{
    const int t = blockIdx.x, b = blockIdx.y, s = blockIdx.z;
    const size_t tb = (size_t)b*Cc*Nn + (size_t)s*(Nn/SPL);
    tc_gemm_tile(g_cT + tb, Nn,
                 g_xTh + tb, g_xTl + tb, Nn,
                 Nn/SPL, (t >> 2)*128, (t & 3)*128,
                 nullptr,
                 g_Gpart + ((size_t)s*Bb + b)*Cc*Cc, Cc);
}

__global__ __launch_bounds__(256)
void T_tc()
{
    const int b = blockIdx.z;
    tc_gemm_tile(g_Wq, Cc,
                 g_Gth + (size_t)b*Cc*Cc, g_Gtl + (size_t)b*Cc*Cc, Cc,
                 Cc, blockIdx.x*128, blockIdx.y*128,
                 nullptr, g_T + (size_t)b*Cc*Cc, Cc);
}

__global__ __launch_bounds__(256)
void w2_tc()
{
    const int b = blockIdx.z;
    tc_gemm_tile(g_M16 + (size_t)b*Cc*Cc, Cc,
                 g_WvTh, g_WvTl, Cc,
                 Cc, blockIdx.x*128, blockIdx.y*128,
                 nullptr, g_W2f + (size_t)b*Cc*Cc, Cc);
}

__global__ __launch_bounds__(256)
void out_tc(float* __restrict__ out)
{
    const int row0 = blockIdx.x*128;
    const int b = row0 >> 13;
    tc_gemm_tile(g_ch, Cc,
                 g_W2h + (size_t)b*Cc*Cc, g_W2l + (size_t)b*Cc*Cc, Cc,
                 Cc, row0, blockIdx.y*128,
                 g_b2 + (size_t)b*Cc, out, Cc);
}

// ---------------------------------------------------------------------------
// Conversion kernels
// ---------------------------------------------------------------------------
__global__ void conv_wq_kernel(const float* __restrict__ Wq)
{
    const size_t i = ((size_t)blockIdx.x*256 + threadIdx.x)*4;
    uint2 h;
    f4_to_h16(*(const float4*)(Wq + i), h);
    *(uint2*)(g_Wq + i) = h;
}

// x -> xT h/l ; ctx -> cT single + g_ch (fused non-transposed fp16 copy)
__global__ void convT_kernel(const float* __restrict__ x, const float* __restrict__ ctx)
{
    const int z = blockIdx.z;
    const int b = z & 3;
    const bool isx = (z < 4);
    const float* src = isx ? x : ctx;
    const int n0 = blockIdx.x*32, c0 = blockIdx.y*32;
    __shared__ float t[32][33];
    const int tx = threadIdx.x & 31, ty = threadIdx.x >> 5;
    #pragma unroll
    for (int r = 0; r < 4; ++r) {
        const size_t si = ((size_t)b*Nn + n0 + ty + r*8)*Cc + c0 + tx;
        const float v = src[si];
        t[ty + r*8][tx] = v;
        if (!isx) g_ch[si] = __float2half_rn(v);   // fused conv_ctx
    }
    __syncthreads();
    #pragma unroll
    for (int r = 0; r < 4; ++r) {
        const float v = t[tx][ty + r*8];
        const __half h = __float2half_rn(v);
        const size_t o = ((size_t)b*Cc + c0 + ty + r*8)*Nn + n0 + tx;
        if (isx) {
            g_xTh[o] = h;
            g_xTl[o] = __float2half_rn(v - __half2float(h));
        } else {
            g_cT[o] = h;
        }
    }
}

// Wv[k][c2] -> WvT[c2][k] h/l
__global__ void convT_wv_kernel(const float* __restrict__ Wv)
{
    const int k0 = blockIdx.x*32, c0 = blockIdx.y*32;
    __shared__ float t[32][33];
    const int tx = threadIdx.x & 31, ty = threadIdx.x >> 5;
    #pragma unroll
    for (int r = 0; r < 4; ++r)
        t[ty + r*8][tx] = Wv[(size_t)(k0 + ty + r*8)*Cc + c0 + tx];
    __syncthreads();
    #pragma unroll
    for (int r = 0; r < 4; ++r) {
        const float v = t[tx][ty + r*8];
        const __half h = __float2half_rn(v);
        const size_t o = (size_t)(c0 + ty + r*8)*Cc + k0 + tx;
        g_WvTh[o] = h;
        g_WvTl[o] = __float2half_rn(v - __half2float(h));
    }
}

__global__ void sreduce_kernel()
{
    const size_t i4 = ((size_t)blockIdx.x*256 + threadIdx.x)*4;
    const size_t stride = (size_t)Bb*Cc*Cc;
    float4 a = *(const float4*)&g_Gpart[i4];
    #pragma unroll
    for (int s = 1; s < SPL; ++s) {
        float4 p = *(const float4*)&g_Gpart[s*stride + i4];
        a.x += p.x; a.y += p.y; a.z += p.z; a.w += p.w;
    }
    uint2 h, l;
    f4_to_hl16(a, h, l);
    *(uint2*)(g_Gth + i4) = h;
    *(uint2*)(g_Gtl + i4) = l;
}

__global__ void conv_w2_kernel()
{
    const size_t i = ((size_t)blockIdx.x*256 + threadIdx.x)*4;
    uint2 h, l;
    f4_to_hl16(*(const float4*)(g_W2f + i), h, l);
    *(uint2*)(g_W2h + i) = h;
    *(uint2*)(g_W2l + i) = l;
}

// ---------------------------------------------------------------------------
// colsum
// ---------------------------------------------------------------------------
__global__ void colsum_part_kernel(const float* __restrict__ x, const float* __restrict__ ctx)
{
    const int z = blockIdx.z;
    const int sid = z >> 5, chunk = z & 31;
    const float* src = sid ? ctx : x;
    const int b = blockIdx.y;
    const int c = blockIdx.x*128 + threadIdx.x;
    const float* p = src + (size_t)b*Nn*Cc + (size_t)chunk*(Nn/32)*Cc + c;
    float s = 0.f;
    #pragma unroll 8
    for (int n = 0; n < Nn/32; ++n) s += p[(size_t)n*Cc];
    g_cspart[sid][chunk][b][c] = s;
}

__global__ void colsum_red_kernel()
{
    const int sid = blockIdx.z;
    const int b = blockIdx.y;
    const int c = blockIdx.x*128 + threadIdx.x;
    float s = 0.f;
    #pragma unroll
    for (int k = 0; k < 32; ++k) s += g_cspart[sid][k][b][c];
    if (sid) g_sc[b][c] = s; else g_sx[b][c] = s;
}

// ---------------------------------------------------------------------------
// att: logits + rank-1 bias terms + softmax (fp32, proven)
// ---------------------------------------------------------------------------
#define TSROW 68

__global__ __launch_bounds__(256)
void att_kernel(const float* __restrict__ Wq, const float* __restrict__ bq_,
                const float* __restrict__ Wk, const float* __restrict__ bk_,
                float* __restrict__ att_out)
{
    const int bh = blockIdx.x;
    const int b = bh >> 3, h = bh & 7, h64 = h * 64;

    __shared__ float Ts[64][TSROW];
    __shared__ float Wks[64][65];
    __shared__ float u[64], w[64];

    const int tid = threadIdx.x;
    const int d = tid >> 2, g = tid & 3;

    if (tid < 64) {
        const float* r = Wq + (size_t)(h64 + tid) * Cc;
        float a = 0.f;
        for (int c = 0; c < Cc; ++c) a = fmaf(r[c], g_sx[b][c], a);
        u[tid] = a;
    } else if (tid < 128) {
        const int e = tid - 64;
        const float* r = Wk + (size_t)(h64 + e) * Cc;
        float a = 0.f;
        for (int c = 0; c < Cc; ++c) a = fmaf(r[c], g_sc[b][c], a);
        w[e] = a;
    }

    float acc[16];
    #pragma unroll
    for (int j = 0; j < 16; ++j) acc[j] = 0.f;

    for (int k0 = 0; k0 < Cc; k0 += 64) {
        __syncthreads();
        for (int i = tid; i < 64*16; i += 256) {
            const int row = i >> 4, c4 = (i & 15) << 2;
            float4 tv = *(const float4*)&g_T[((size_t)b*Cc + h64 + row)*Cc + k0 + c4];
            *(float4*)&Ts[row][c4] = tv;
            float4 wv = *(const float4*)&Wk[(size_t)(h64 + row)*Cc + k0 + c4];
            Wks[c4+0][row] = wv.x; Wks[c4+1][row] = wv.y;
            Wks[c4+2][row] = wv.z; Wks[c4+3][row] = wv.w;
        }
        __syncthreads();
        #pragma unroll 16
        for (int k = 0; k < 64; ++k) {
            const float tv = Ts[d][k];
            #pragma unroll
            for (int j = 0; j < 16; ++j)
                acc[j] = fmaf(tv, Wks[k][g*16 + j], acc[j]);
        }
    }
    __syncthreads();

    const float bqd = bq_[h64 + d];
    const float ud  = u[d];
    float v[16];
    #pragma unroll
    for (int j = 0; j < 16; ++j) {
        const int e = g*16 + j;
        const float l = acc[j] + bqd * w[e] + bk_[h64 + e] * ud
                      + (float)Nn * bqd * bk_[h64 + e];
        v[j] = l * 0.125f;
    }

    float mx = v[0];
    #pragma unroll
    for (int j = 1; j < 16; ++j) mx = fmaxf(mx, v[j]);
    mx = fmaxf(mx, __shfl_xor_sync(0xffffffff, mx, 1));
    mx = fmaxf(mx, __shfl_xor_sync(0xffffffff, mx, 2));
    float sum = 0.f;
    #pragma unroll
    for (int j = 0; j < 16; ++j) { v[j] = expf(v[j] - mx); sum += v[j]; }
    sum += __shfl_xor_sync(0xffffffff, sum, 1);
    sum += __shfl_xor_sync(0xffffffff, sum, 2);
    const float inv = 1.f / sum;

    const size_t base = ((size_t)bh*64 + d)*64 + g*16;
    #pragma unroll
    for (int q = 0; q < 4; ++q) {
        float4 o;
        o.x = v[q*4+0]*inv; o.y = v[q*4+1]*inv;
        o.z = v[q*4+2]*inv; o.w = v[q*4+3]*inv;
        *(float4*)&g_att[base + q*4] = o;
        if (att_out) *(float4*)&att_out[base + q*4] = o;
    }
}

// ---------------------------------------------------------------------------
// buildM: writes fp32 (for b2) + fp16 (for w2_tc)
// ---------------------------------------------------------------------------
__global__ __launch_bounds__(256)
void buildM_kernel(const float* __restrict__ proj_w)
{
    const int b   = blockIdx.x;
    const int cp0 = blockIdx.y * 64;
    __shared__ float atts[64][65];
    const int tid = threadIdx.x;

    for (int h = 0; h < Hh; ++h) {
        for (int i = tid; i < 64*64; i += 256) {
            const int d2 = i >> 6, e = i & 63;
            atts[d2][e] = g_att[(((size_t)(b*Hh + h)*64) + d2)*64 + e];
        }
        __syncthreads();
        for (int ww = tid; ww < 64*16; ww += 256) {
            const int cp = cp0 + (ww >> 4);
            const int e4 = (ww & 15) << 2;
            const float* pw = proj_w + (size_t)cp*Cc + h*64;
            float a0=0.f, a1=0.f, a2=0.f, a3=0.f;
            #pragma unroll 16
            for (int d2 = 0; d2 < 64; ++d2) {
                const float p = pw[d2];
                a0 = fmaf(p, atts[d2][e4+0], a0);
                a1 = fmaf(p, atts[d2][e4+1], a1);
                a2 = fmaf(p, atts[d2][e4+2], a2);
                a3 = fmaf(p, atts[d2][e4+3], a3);
            }
            const size_t o = (((size_t)b*Cc + cp)*Cc) + h*64 + e4;
            float4 vv; vv.x=a0; vv.y=a1; vv.z=a2; vv.w=a3;
            *(float4*)&g_M[o] = vv;
            uint2 hh;
            f4_to_h16(vv, hh);
            *(uint2*)(g_M16 + o) = hh;
        }
        __syncthreads();
    }
}

// b2[b][cp] = proj_b[cp] + sum_j M[b][cp][j] * bv[j]
__global__ void b2_kernel(const float* __restrict__ bv, const float* __restrict__ proj_b)
{
    const int b  = blockIdx.x;
    const int cp = threadIdx.x;   // 512
    const float* m = g_M + ((size_t)b*Cc + cp)*Cc;
    float s = proj_b[cp];
    for (int j = 0; j < Cc; ++j) s = fmaf(m[j], bv[j], s);
    g_b2[b*Cc + cp] = s;
}

// ---------------------------------------------------------------------------
extern "C" void kernel_launch(void* const* d_in, const int* in_sizes, int n_in,
                              void* d_out, int out_size)
{
    const float* x      = (const float*)d_in[0];
    const float* ctx    = (const float*)d_in[1];
    const float* Wq     = (const float*)d_in[2];
    const float* bq     = (const float*)d_in[3];
    const float* Wk     = (const float*)d_in[4];
    const float* bk     = (const float*)d_in[5];
    const float* Wv     = (const float*)d_in[6];
    const float* bv     = (const float*)d_in[7];
    const float* proj_w = (const float*)d_in[8];
    const float* proj_b = (const float*)d_in[9];
    float* out = (float*)d_out;

    float* att_out = (out_size >= OUT_ELEMS + ATT_ELEMS) ? (out + OUT_ELEMS) : nullptr;

    convT_kernel      <<<dim3(Nn/32, Cc/32, 8), 256>>>(x, ctx);   // 1 (also writes g_ch)
    conv_wq_kernel    <<<256, 256>>>(Wq);                         // 2
    colsum_part_kernel<<<dim3(Cc/128, Bb, 64), 128>>>(x, ctx);    // 3
    spart_tc          <<<dim3(16, Bb, SPL), 256>>>();             // 4 (profiled)
    colsum_red_kernel <<<dim3(Cc/128, Bb, 2), 128>>>();           // 5
    convT_wv_kernel   <<<dim3(16, 16), 256>>>(Wv);                // 6
    sreduce_kernel    <<<1024, 256>>>();                          // 7
    T_tc              <<<dim3(Cc/128, Cc/128, Bb), 256>>>();      // 8
    att_kernel        <<<Bb*Hh, 256>>>(Wq, bq, Wk, bk, att_out);  // 9
    buildM_kernel     <<<dim3(Bb, Cc/64), 256>>>(proj_w);         // 10
    w2_tc             <<<dim3(Cc/128, Cc/128, Bb), 256>>>();      // 11
    conv_w2_kernel    <<<1024, 256>>>();                          // 12
    b2_kernel         <<<Bb, 512>>>(bv, proj_b);                  // 13
    out_tc            <<<dim3(Bb*Nn/128, Cc/128), 256>>>(out);    // 14
}

// round 17
// speedup vs baseline: 1.5515x; 1.0338x over previous
#include <cuda_runtime.h>
#include <cuda_fp16.h>
#include <cstdint>
#include <math.h>

#define Bb 4
#define Nn 8192
#define Cc 512
#define Hh 8
#define Dd 64
#define SPL 8
#define OUT_ELEMS (Bb*Nn*Cc)
#define ATT_ELEMS (Bb*Hh*Dd*Dd)

// ---------------------------------------------------------------------------
// Static scratch
// ---------------------------------------------------------------------------
__device__ float g_Gpart[SPL*Bb*Cc*Cc];
__device__ float g_T[Bb*Cc*Cc];
__device__ float g_att[ATT_ELEMS];
__device__ float g_M[Bb*Cc*Cc];
__device__ float g_W2f[Bb*Cc*Cc];
__device__ float g_b2[Bb*Cc];
__device__ float g_sx[Bb][Cc];
__device__ float g_sc[Bb][Cc];

__device__ __half g_ch[Bb*Nn*Cc];                       // ctx (K=c major, single)
__device__ __half g_cT[Bb*Cc*Nn];                       // ctx^T (single)
__device__ __half g_xTh[Bb*Cc*Nn], g_xTl[Bb*Cc*Nn];    // x^T h/l
__device__ __half g_Gth[Bb*Cc*Cc], g_Gtl[Bb*Cc*Cc];    // Gt h/l
__device__ __half g_Wq[Cc*Cc];
__device__ __half g_M16[Bb*Cc*Cc];
__device__ __half g_WvTh[Cc*Cc], g_WvTl[Cc*Cc];
__device__ __half g_W2h[Bb*Cc*Cc], g_W2l[Bb*Cc*Cc];

// ---------------------------------------------------------------------------
// mma.sync m16n8k16 f16 + ldmatrix + cp.async
// ---------------------------------------------------------------------------
__device__ __forceinline__ void mma16816(float* c, const uint32_t* a, const uint32_t* b)
{
    asm volatile(
        "mma.sync.aligned.m16n8k16.row.col.f32.f16.f16.f32 "
        "{%0,%1,%2,%3}, {%4,%5,%6,%7}, {%8,%9}, {%0,%1,%2,%3};"
        : "+f"(c[0]), "+f"(c[1]), "+f"(c[2]), "+f"(c[3])
        : "r"(a[0]), "r"(a[1]), "r"(a[2]), "r"(a[3]), "r"(b[0]), "r"(b[1]));
}
__device__ __forceinline__ void ldsm_x4(uint32_t* r, const __half* p)
{
    uint32_t addr = (uint32_t)__cvta_generic_to_shared(p);
    asm volatile("ldmatrix.sync.aligned.m8n8.x4.shared.b16 {%0,%1,%2,%3}, [%4];"
                 : "=r"(r[0]), "=r"(r[1]), "=r"(r[2]), "=r"(r[3]) : "r"(addr));
}
__device__ __forceinline__ void cp16(const __half* smem_dst, const __half* gmem_src)
{
    uint32_t d = (uint32_t)__cvta_generic_to_shared(smem_dst);
    asm volatile("cp.async.cg.shared.global [%0], [%1], 16;" :: "r"(d), "l"(gmem_src));
}
__device__ __forceinline__ void f4_to_h16(float4 v, uint2& h)
{
    __half h0 = __float2half_rn(v.x), h1 = __float2half_rn(v.y);
    __half h2 = __float2half_rn(v.z), h3 = __float2half_rn(v.w);
    h.x = (uint32_t)__half_as_ushort(h0) | ((uint32_t)__half_as_ushort(h1) << 16);
    h.y = (uint32_t)__half_as_ushort(h2) | ((uint32_t)__half_as_ushort(h3) << 16);
}
__device__ __forceinline__ void f4_to_hl16(float4 v, uint2& h, uint2& l)
{
    __half h0 = __float2half_rn(v.x), h1 = __float2half_rn(v.y);
    __half h2 = __float2half_rn(v.z), h3 = __float2half_rn(v.w);
    __half l0 = __float2half_rn(v.x - __half2float(h0));
    __half l1 = __float2half_rn(v.y - __half2float(h1));
    __half l2 = __float2half_rn(v.z - __half2float(h2));
    __half l3 = __float2half_rn(v.w - __half2float(h3));
    h.x = (uint32_t)__half_as_ushort(h0) | ((uint32_t)__half_as_ushort(h1) << 16);
    h.y = (uint32_t)__half_as_ushort(h2) | ((uint32_t)__half_as_ushort(h3) << 16);
    l.x = (uint32_t)__half_as_ushort(l0) | ((uint32_t)__half_as_ushort(l1) << 16);
    l.y = (uint32_t)__half_as_ushort(l2) | ((uint32_t)__half_as_ushort(l3) << 16);
}

// ---------------------------------------------------------------------------
// GEMM tile: D[128x128] = sum_k A[128,K] B[128,K]^T.
// fp16 asymmetric split-2 (A single, B = Bh+Bl). cp.async double-buffered:
// Kc=16, SK=24 (conflict-free), 2x3 tiles = 36KB static smem, 1 sync/chunk.
// 256 thr, 8 warps 32x64, fp32 epilogue (+bias).  (R16-proven)
// ---------------------------------------------------------------------------
#define SK 24
#define TILE_ELEMS (128*SK)

__device__ void tc_gemm_tile(
    const __half* __restrict__ A, int lda,
    const __half* __restrict__ Bh, const __half* __restrict__ Bl, int ldb,
    int K, int row0, int col0,
    const float* __restrict__ bias,
    float* __restrict__ outF, int ldo)
{
    __shared__ __half sm[2][3*TILE_ELEMS];   // 36864 B static

    const int tid  = threadIdx.x;
    const int lane = tid & 31;
    const int wid  = tid >> 5;
    const int wm   = wid >> 1;
    const int wn   = wid & 1;
    const int gr   = lane >> 2;
    const int kp   = (lane & 3) << 1;
    const int lrow = lane & 15;
    const int lkof = (lane >> 4) * 8;

    const int crow = tid >> 1;
    const int cseg = (tid & 1) * 8;

    const __half* srcA  = A  + (size_t)(row0 + crow)*lda + cseg;
    const __half* srcBh = Bh + (size_t)(col0 + crow)*ldb + cseg;
    const __half* srcBl = Bl + (size_t)(col0 + crow)*ldb + cseg;
    const int dstoff = crow*SK + cseg;

    float acc[64];
    #pragma unroll
    for (int i = 0; i < 64; ++i) acc[i] = 0.f;

    const int nch = K / 16;

    cp16(&sm[0][0*TILE_ELEMS + dstoff], srcA);
    cp16(&sm[0][1*TILE_ELEMS + dstoff], srcBh);
    cp16(&sm[0][2*TILE_ELEMS + dstoff], srcBl);
    asm volatile("cp.async.commit_group;" ::: "memory");
    asm volatile("cp.async.wait_group 0;" ::: "memory");
    __syncthreads();

    for (int c = 0; c < nch; ++c) {
        const int buf = c & 1;
        if (c + 1 < nch) {
            const int k0 = (c + 1) * 16;
            const int nb = (c + 1) & 1;
            cp16(&sm[nb][0*TILE_ELEMS + dstoff], srcA  + k0);
            cp16(&sm[nb][1*TILE_ELEMS + dstoff], srcBh + k0);
            cp16(&sm[nb][2*TILE_ELEMS + dstoff], srcBl + k0);
            asm volatile("cp.async.commit_group;" ::: "memory");
        }

        const __half* sA  = &sm[buf][0*TILE_ELEMS];
        const __half* sBh = &sm[buf][1*TILE_ELEMS];
        const __half* sBl = &sm[buf][2*TILE_ELEMS];

        uint32_t ah[2][4];
        #pragma unroll
        for (int mt = 0; mt < 2; ++mt) {
            const int m0 = wm*32 + mt*16;
            ldsm_x4(ah[mt], sA + (m0 + lrow)*SK + lkof);
        }
        #pragma unroll
        for (int nt2 = 0; nt2 < 4; ++nt2) {
            const int n0 = wn*64 + nt2*16;
            uint32_t bh4[4], bl4[4];
            ldsm_x4(bh4, sBh + (n0 + lrow)*SK + lkof);
            ldsm_x4(bl4, sBl + (n0 + lrow)*SK + lkof);
            uint32_t bhE[2] = {bh4[0], bh4[2]}, bhO[2] = {bh4[1], bh4[3]};
            uint32_t blE[2] = {bl4[0], bl4[2]}, blO[2] = {bl4[1], bl4[3]};
            #pragma unroll
            for (int mt = 0; mt < 2; ++mt) {
                float* ccE = &acc[(mt*8 + 2*nt2    )*4];
                float* ccO = &acc[(mt*8 + 2*nt2 + 1)*4];
                mma16816(ccE, ah[mt], bhE);
                mma16816(ccE, ah[mt], blE);
                mma16816(ccO, ah[mt], bhO);
                mma16816(ccO, ah[mt], blO);
            }
        }

        asm volatile("cp.async.wait_group 0;" ::: "memory");
        __syncthreads();
    }

    #pragma unroll
    for (int mt = 0; mt < 2; ++mt) {
        const int r0 = row0 + wm*32 + mt*16 + gr;
        #pragma unroll
        for (int nt = 0; nt < 8; ++nt) {
            const int col = col0 + wn*64 + nt*8 + kp;
            const float* cc = &acc[(mt*8 + nt)*4];
            float b0 = bias ? bias[col]     : 0.f;
            float b1 = bias ? bias[col + 1] : 0.f;
            *(float2*)(outF + (size_t)r0*ldo + col)     = make_float2(cc[0] + b0, cc[1] + b1);
            *(float2*)(outF + (size_t)(r0+8)*ldo + col) = make_float2(cc[2] + b0, cc[3] + b1);
        }
    }
}

// ---------------------------------------------------------------------------
// GEMM wrapper kernels
// ---------------------------------------------------------------------------
__global__ __launch_bounds__(256)
void spart_tc()
{
    const int t = blockIdx.x, b = blockIdx.y, s = blockIdx.z;
    const size_t tb = (size_t)b*Cc*Nn + (size_t)s*(Nn/SPL);
    tc_gemm_tile(g_cT + tb, Nn,
                 g_xTh + tb, g_xTl + tb, Nn,
                 Nn/SPL, (t >> 2)*128, (t & 3)*128,
                 nullptr,
                 g_Gpart + ((size_t)s*Bb + b)*Cc*Cc, Cc);
}

__global__ __launch_bounds__(256)
void T_tc()
{
    const int b = blockIdx.z;
    tc_gemm_tile(g_Wq, Cc,
                 g_Gth + (size_t)b*Cc*Cc, g_Gtl + (size_t)b*Cc*Cc, Cc,
                 Cc, blockIdx.x*128, blockIdx.y*128,
                 nullptr, g_T + (size_t)b*Cc*Cc, Cc);
}

__global__ __launch_bounds__(256)
void w2_tc()
{
    const int b = blockIdx.z;
    tc_gemm_tile(g_M16 + (size_t)b*Cc*Cc, Cc,
                 g_WvTh, g_WvTl, Cc,
                 Cc, blockIdx.x*128, blockIdx.y*128,
                 nullptr, g_W2f + (size_t)b*Cc*Cc, Cc);
}

__global__ __launch_bounds__(256)
void out_tc(float* __restrict__ out)
{
    const int row0 = blockIdx.x*128;
    const int b = row0 >> 13;
    tc_gemm_tile(g_ch, Cc,
                 g_W2h + (size_t)b*Cc*Cc, g_W2l + (size_t)b*Cc*Cc, Cc,
                 Cc, row0, blockIdx.y*128,
                 g_b2 + (size_t)b*Cc, out, Cc);
}

// ---------------------------------------------------------------------------
// Conversion kernels
// ---------------------------------------------------------------------------
__global__ void zero_sums_kernel()
{
    const int i = threadIdx.x;              // 512
    #pragma unroll
    for (int b = 0; b < Bb; ++b) { g_sx[b][i] = 0.f; g_sc[b][i] = 0.f; }
}

__global__ void conv_wq_kernel(const float* __restrict__ Wq)
{
    const size_t i = ((size_t)blockIdx.x*256 + threadIdx.x)*4;
    uint2 h;
    f4_to_h16(*(const float4*)(Wq + i), h);
    *(uint2*)(g_Wq + i) = h;
}

// x -> xT h/l (+ colsum x); ctx -> cT + g_ch (+ colsum ctx)
__global__ void convT_kernel(const float* __restrict__ x, const float* __restrict__ ctx)
{
    const int z = blockIdx.z;
    const int b = z & 3;
    const bool isx = (z < 4);
    const float* src = isx ? x : ctx;
    const int n0 = blockIdx.x*32, c0 = blockIdx.y*32;
    __shared__ float t[32][33];
    const int tx = threadIdx.x & 31, ty = threadIdx.x >> 5;
    #pragma unroll
    for (int r = 0; r < 4; ++r) {
        const size_t si = ((size_t)b*Nn + n0 + ty + r*8)*Cc + c0 + tx;
        const float v = src[si];
        t[ty + r*8][tx] = v;
        if (!isx) g_ch[si] = __float2half_rn(v);
    }
    __syncthreads();
    // fused colsum: warp 0 sums the 32 n-rows of each column, one atomic per col
    if (ty == 0) {
        float s = 0.f;
        #pragma unroll
        for (int r = 0; r < 32; ++r) s += t[r][tx];
        atomicAdd(isx ? &g_sx[b][c0 + tx] : &g_sc[b][c0 + tx], s);
    }
    #pragma unroll
    for (int r = 0; r < 4; ++r) {
        const float v = t[tx][ty + r*8];
        const __half h = __float2half_rn(v);
        const size_t o = ((size_t)b*Cc + c0 + ty + r*8)*Nn + n0 + tx;
        if (isx) {
            g_xTh[o] = h;
            g_xTl[o] = __float2half_rn(v - __half2float(h));
        } else {
            g_cT[o] = h;
        }
    }
}

// Wv[k][c2] -> WvT[c2][k] h/l
__global__ void convT_wv_kernel(const float* __restrict__ Wv)
{
    const int k0 = blockIdx.x*32, c0 = blockIdx.y*32;
    __shared__ float t[32][33];
    const int tx = threadIdx.x & 31, ty = threadIdx.x >> 5;
    #pragma unroll
    for (int r = 0; r < 4; ++r)
        t[ty + r*8][tx] = Wv[(size_t)(k0 + ty + r*8)*Cc + c0 + tx];
    __syncthreads();
    #pragma unroll
    for (int r = 0; r < 4; ++r) {
        const float v = t[tx][ty + r*8];
        const __half h = __float2half_rn(v);
        const size_t o = (size_t)(c0 + ty + r*8)*Cc + k0 + tx;
        g_WvTh[o] = h;
        g_WvTl[o] = __float2half_rn(v - __half2float(h));
    }
}

__global__ void sreduce_kernel()
{
    const size_t i4 = ((size_t)blockIdx.x*256 + threadIdx.x)*4;
    const size_t stride = (size_t)Bb*Cc*Cc;
    float4 a = *(const float4*)&g_Gpart[i4];
    #pragma unroll
    for (int s = 1; s < SPL; ++s) {
        float4 p = *(const float4*)&g_Gpart[s*stride + i4];
        a.x += p.x; a.y += p.y; a.z += p.z; a.w += p.w;
    }
    uint2 h, l;
    f4_to_hl16(a, h, l);
    *(uint2*)(g_Gth + i4) = h;
    *(uint2*)(g_Gtl + i4) = l;
}

__global__ void conv_w2_kernel()
{
    const size_t i = ((size_t)blockIdx.x*256 + threadIdx.x)*4;
    uint2 h, l;
    f4_to_hl16(*(const float4*)(g_W2f + i), h, l);
    *(uint2*)(g_W2h + i) = h;
    *(uint2*)(g_W2l + i) = l;
}

// ---------------------------------------------------------------------------
// att: logits + rank-1 bias terms + softmax (fp32, proven)
// ---------------------------------------------------------------------------
#define TSROW 68

__global__ __launch_bounds__(256)
void att_kernel(const float* __restrict__ Wq, const float* __restrict__ bq_,
                const float* __restrict__ Wk, const float* __restrict__ bk_,
                float* __restrict__ att_out)
{
    const int bh = blockIdx.x;
    const int b = bh >> 3, h = bh & 7, h64 = h * 64;

    __shared__ float Ts[64][TSROW];
    __shared__ float Wks[64][65];
    __shared__ float u[64], w[64];

    const int tid = threadIdx.x;
    const int d = tid >> 2, g = tid & 3;

    if (tid < 64) {
        const float* r = Wq + (size_t)(h64 + tid) * Cc;
        float a = 0.f;
        for (int c = 0; c < Cc; ++c) a = fmaf(r[c], g_sx[b][c], a);
        u[tid] = a;
    } else if (tid < 128) {
        const int e = tid - 64;
        const float* r = Wk + (size_t)(h64 + e) * Cc;
        float a = 0.f;
        for (int c = 0; c < Cc; ++c) a = fmaf(r[c], g_sc[b][c], a);
        w[e] = a;
    }

    float acc[16];
    #pragma unroll
    for (int j = 0; j < 16; ++j) acc[j] = 0.f;

    for (int k0 = 0; k0 < Cc; k0 += 64) {
        __syncthreads();
        for (int i = tid; i < 64*16; i += 256) {
            const int row = i >> 4, c4 = (i & 15) << 2;
            float4 tv = *(const float4*)&g_T[((size_t)b*Cc + h64 + row)*Cc + k0 + c4];
            *(float4*)&Ts[row][c4] = tv;
            float4 wv = *(const float4*)&Wk[(size_t)(h64 + row)*Cc + k0 + c4];
            Wks[c4+0][row] = wv.x; Wks[c4+1][row] = wv.y;
            Wks[c4+2][row] = wv.z; Wks[c4+3][row] = wv.w;
        }
        __syncthreads();
        #pragma unroll 16
        for (int k = 0; k < 64; ++k) {
            const float tv = Ts[d][k];
            #pragma unroll
            for (int j = 0; j < 16; ++j)
                acc[j] = fmaf(tv, Wks[k][g*16 + j], acc[j]);
        }
    }
    __syncthreads();

    const float bqd = bq_[h64 + d];
    const float ud  = u[d];
    float v[16];
    #pragma unroll
    for (int j = 0; j < 16; ++j) {
        const int e = g*16 + j;
        const float l = acc[j] + bqd * w[e] + bk_[h64 + e] * ud
                      + (float)Nn * bqd * bk_[h64 + e];
        v[j] = l * 0.125f;
    }

    float mx = v[0];
    #pragma unroll
    for (int j = 1; j < 16; ++j) mx = fmaxf(mx, v[j]);
    mx = fmaxf(mx, __shfl_xor_sync(0xffffffff, mx, 1));
    mx = fmaxf(mx, __shfl_xor_sync(0xffffffff, mx, 2));
    float sum = 0.f;
    #pragma unroll
    for (int j = 0; j < 16; ++j) { v[j] = expf(v[j] - mx); sum += v[j]; }
    sum += __shfl_xor_sync(0xffffffff, sum, 1);
    sum += __shfl_xor_sync(0xffffffff, sum, 2);
    const float inv = 1.f / sum;

    const size_t base = ((size_t)bh*64 + d)*64 + g*16;
    #pragma unroll
    for (int q = 0; q < 4; ++q) {
        float4 o;
        o.x = v[q*4+0]*inv; o.y = v[q*4+1]*inv;
        o.z = v[q*4+2]*inv; o.w = v[q*4+3]*inv;
        *(float4*)&g_att[base + q*4] = o;
        if (att_out) *(float4*)&att_out[base + q*4] = o;
    }
}

// ---------------------------------------------------------------------------
// buildM: writes fp32 (for b2) + fp16 (for w2_tc)
// ---------------------------------------------------------------------------
__global__ __launch_bounds__(256)
void buildM_kernel(const float* __restrict__ proj_w)
{
    const int b   = blockIdx.x;
    const int cp0 = blockIdx.y * 64;
    __shared__ float atts[64][65];
    const int tid = threadIdx.x;

    for (int h = 0; h < Hh; ++h) {
        for (int i = tid; i < 64*64; i += 256) {
            const int d2 = i >> 6, e = i & 63;
            atts[d2][e] = g_att[(((size_t)(b*Hh + h)*64) + d2)*64 + e];
        }
        __syncthreads();
        for (int ww = tid; ww < 64*16; ww += 256) {
            const int cp = cp0 + (ww >> 4);
            const int e4 = (ww & 15) << 2;
            const float* pw = proj_w + (size_t)cp*Cc + h*64;
            float a0=0.f, a1=0.f, a2=0.f, a3=0.f;
            #pragma unroll 16
            for (int d2 = 0; d2 < 64; ++d2) {
                const float p = pw[d2];
                a0 = fmaf(p, atts[d2][e4+0], a0);
                a1 = fmaf(p, atts[d2][e4+1], a1);
                a2 = fmaf(p, atts[d2][e4+2], a2);
                a3 = fmaf(p, atts[d2][e4+3], a3);
            }
            const size_t o = (((size_t)b*Cc + cp)*Cc) + h*64 + e4;
            float4 vv; vv.x=a0; vv.y=a1; vv.z=a2; vv.w=a3;
            *(float4*)&g_M[o] = vv;
            uint2 hh;
            f4_to_h16(vv, hh);
            *(uint2*)(g_M16 + o) = hh;
        }
        __syncthreads();
    }
}

// b2[b][cp] = proj_b[cp] + sum_j M[b][cp][j] * bv[j]
__global__ void b2_kernel(const float* __restrict__ bv, const float* __restrict__ proj_b)
{
    const int b  = blockIdx.x;
    const int cp = threadIdx.x;   // 512
    const float* m = g_M + ((size_t)b*Cc + cp)*Cc;
    float s = proj_b[cp];
    for (int j = 0; j < Cc; ++j) s = fmaf(m[j], bv[j], s);
    g_b2[b*Cc + cp] = s;
}

// ---------------------------------------------------------------------------
extern "C" void kernel_launch(void* const* d_in, const int* in_sizes, int n_in,
                              void* d_out, int out_size)
{
    const float* x      = (const float*)d_in[0];
    const float* ctx    = (const float*)d_in[1];
    const float* Wq     = (const float*)d_in[2];
    const float* bq     = (const float*)d_in[3];
    const float* Wk     = (const float*)d_in[4];
    const float* bk     = (const float*)d_in[5];
    const float* Wv     = (const float*)d_in[6];
    const float* bv     = (const float*)d_in[7];
    const float* proj_w = (const float*)d_in[8];
    const float* proj_b = (const float*)d_in[9];
    float* out = (float*)d_out;

    float* att_out = (out_size >= OUT_ELEMS + ATT_ELEMS) ? (out + OUT_ELEMS) : nullptr;

    zero_sums_kernel  <<<1, 512>>>();                             // 1
    convT_kernel      <<<dim3(Nn/32, Cc/32, 8), 256>>>(x, ctx);   // 2 (xT/cT/g_ch + colsums)
    conv_wq_kernel    <<<256, 256>>>(Wq);                         // 3
    spart_tc          <<<dim3(16, Bb, SPL), 256>>>();             // 4 (profiled)
    convT_wv_kernel   <<<dim3(16, 16), 256>>>(Wv);                // 5
    sreduce_kernel    <<<1024, 256>>>();                          // 6
    T_tc              <<<dim3(Cc/128, Cc/128, Bb), 256>>>();      // 7
    att_kernel        <<<Bb*Hh, 256>>>(Wq, bq, Wk, bk, att_out);  // 8
    buildM_kernel     <<<dim3(Bb, Cc/64), 256>>>(proj_w);         // 9
    w2_tc             <<<dim3(Cc/128, Cc/128, Bb), 256>>>();      // 10
    conv_w2_kernel    <<<1024, 256>>>();                          // 11
    b2_kernel         <<<Bb, 512>>>(bv, proj_b);                  // 12
    out_tc            <<<dim3(Bb*Nn/128, Cc/128), 256>>>(out);    // 13
}